// round 1
// baseline (speedup 1.0000x reference)
#include <cuda_runtime.h>
#include <cuda_bf16.h>

#define N_  2048
#define L_  2
#define H_  4
#define D_  16
#define F_  64
#define E_  64
#define C_  32
#define NLH (N_*L_*H_)          // 16384
#define EPS 1e-5f

// Scratch (device globals — no allocation allowed)
__device__ float g_logits[NLH];            // 64 KB
__device__ float g_value [NLH * D_];       // 1 MB
__device__ float g_attn_scratch[C_ * NLH]; // 2 MB fallback if attn not in d_out
__device__ int   g_is64;                   // component_id dtype flag

// ---------------------------------------------------------------------------
// Detect whether component_id is int64 (all high 32-bit words are zero) or
// int32. Values are in [0,32), so for int64 every odd 32-bit word is 0.
// ---------------------------------------------------------------------------
__global__ void detect_dtype_kernel(const int* __restrict__ comp) {
    __shared__ int any;
    if (threadIdx.x == 0) any = 0;
    __syncthreads();
    int v = 0;
    for (int i = threadIdx.x; i < N_; i += blockDim.x) v |= comp[2*i + 1];
    if (v) atomicOr(&any, 1);
    __syncthreads();
    if (threadIdx.x == 0) g_is64 = (any == 0) ? 1 : 0;
}

__device__ __forceinline__ int load_comp(const int* __restrict__ comp, int n) {
    return g_is64 ? comp[2*n] : comp[n];
}

// ---------------------------------------------------------------------------
// One FFN path for one (n,l,h): lane owns rows f0=2*lane, f1=2*lane+1.
// Returns the LayerNorm'd output element for d = lane (valid for lane < 16).
// spart: per-warp smem scratch of 32*17 floats.
// ---------------------------------------------------------------------------
__device__ __forceinline__ float ffn_ln_path(
    const float* __restrict__ w0, const float* __restrict__ b0,
    const float* __restrict__ w1, const float* __restrict__ b1,
    const float* __restrict__ sfeat, float* spart, int lane,
    float gamma_d, float beta_d)
{
    const int f0 = 2*lane, f1 = f0 + 1;

    // ---- layer 0: h_f = relu(feat . w0[f,:] + b0[f]) ----
    float acc0 = 0.f, acc1 = 0.f;
    const float4* r0 = (const float4*)(w0 + f0 * E_);
    const float4* r1 = (const float4*)(w0 + f1 * E_);
    const float4* sf = (const float4*)sfeat;
#pragma unroll
    for (int i = 0; i < E_/4; i++) {
        float4 a = r0[i], b = r1[i], f = sf[i];
        acc0 = fmaf(a.x, f.x, fmaf(a.y, f.y, fmaf(a.z, f.z, fmaf(a.w, f.w, acc0))));
        acc1 = fmaf(b.x, f.x, fmaf(b.y, f.y, fmaf(b.z, f.z, fmaf(b.w, f.w, acc1))));
    }
    float h0 = fmaxf(acc0 + b0[f0], 0.f);
    float h1 = fmaxf(acc1 + b0[f1], 0.f);

    // ---- layer 1 partials: part[d] = h0*w1[f0,d] + h1*w1[f1,d] ----
    const float4* q0 = (const float4*)(w1 + f0 * D_);
    const float4* q1 = (const float4*)(w1 + f1 * D_);
    float part[D_];
#pragma unroll
    for (int i = 0; i < D_/4; i++) {
        float4 a = q0[i], b = q1[i];
        part[4*i+0] = fmaf(h0, a.x, h1 * b.x);
        part[4*i+1] = fmaf(h0, a.y, h1 * b.y);
        part[4*i+2] = fmaf(h0, a.z, h1 * b.z);
        part[4*i+3] = fmaf(h0, a.w, h1 * b.w);
    }

    // ---- transpose-reduce across lanes via smem (stride 17: conflict-free) ----
    __syncwarp();
#pragma unroll
    for (int d = 0; d < D_; d++) spart[lane*17 + d] = part[d];
    __syncwarp();

    float x = 0.f;
    if (lane < D_) {
#pragma unroll
        for (int j = 0; j < 32; j++) x += spart[j*17 + lane];
        x += b1[lane];
    }
    __syncwarp();

    // ---- LayerNorm over the 16-lane group ----
    float s = x;
#pragma unroll
    for (int off = 8; off >= 1; off >>= 1) s += __shfl_xor_sync(0xffffffffu, s, off);
    float mu = s * (1.f/16.f);
    float dl = x - mu;
    float v = dl * dl;
#pragma unroll
    for (int off = 8; off >= 1; off >>= 1) v += __shfl_xor_sync(0xffffffffu, v, off);
    float var = v * (1.f/16.f);
    return fmaf(dl * rsqrtf(var + EPS), gamma_d, beta_d);
}

// ---------------------------------------------------------------------------
// Kernel 1: per-node FFNs (key + value), logits, LN'd values.
// grid = N*L blocks, 128 threads (warp per head).
// ---------------------------------------------------------------------------
__global__ __launch_bounds__(128) void ffn_kernel(
    const float* __restrict__ feat,  const float* __restrict__ query,
    const float* __restrict__ kw0,   const float* __restrict__ kb0,
    const float* __restrict__ kw1,   const float* __restrict__ kb1,
    const float* __restrict__ vw0,   const float* __restrict__ vb0,
    const float* __restrict__ vw1,   const float* __restrict__ vb1,
    const float* __restrict__ key_gamma, const float* __restrict__ key_beta)
{
    const int nl   = blockIdx.x;
    const int wid  = threadIdx.x >> 5;
    const int lane = threadIdx.x & 31;

    __shared__ float sfeat[E_];
    __shared__ float spart[4 * 32 * 17];

    if (threadIdx.x < E_) sfeat[threadIdx.x] = feat[(size_t)nl * E_ + threadIdx.x];
    __syncthreads();

    const int h    = wid;
    const int nlh  = nl * H_ + h;
    const size_t b0off = (size_t)nlh * (F_ * E_);
    const size_t b1off = (size_t)nlh * (F_ * D_);
    const size_t bboff = (size_t)nlh * F_;
    const size_t bdoff = (size_t)nlh * D_;
    float* my_spart = spart + wid * 32 * 17;

    const float gd = key_gamma[lane & 15];
    const float bd = key_beta [lane & 15];

    // key path -> logits
    float kln = ffn_ln_path(kw0 + b0off, kb0 + bboff, kw1 + b1off, kb1 + bdoff,
                            sfeat, my_spart, lane, gd, bd);
    float p = (lane < D_) ? kln * query[bdoff + lane] : 0.f;
#pragma unroll
    for (int off = 8; off >= 1; off >>= 1) p += __shfl_xor_sync(0xffffffffu, p, off);
    if (lane == 0) g_logits[nlh] = p;

    // value path (note: reference reuses key_gamma/key_beta here)
    float vln = ffn_ln_path(vw0 + b0off, vb0 + bboff, vw1 + b1off, vb1 + bdoff,
                            sfeat, my_spart, lane, gd, bd);
    if (lane < D_) g_value[(size_t)nlh * D_ + lane] = vln;
}

// ---------------------------------------------------------------------------
// Kernel 2: per-component masked softmax over (n,l) jointly per head,
// attention-weighted sum of values, final LayerNorm.
// grid = C blocks, 256 threads. Thread t always handles head h = t & 3.
// ---------------------------------------------------------------------------
__global__ __launch_bounds__(256) void softmax_out_kernel(
    const int* __restrict__ comp,
    const float* __restrict__ out_gamma, const float* __restrict__ out_beta,
    float* __restrict__ out, float* __restrict__ attn_out,
    float* __restrict__ uid_out, int write_attn, int write_uid)
{
    const int c = blockIdx.x;
    const int t = threadIdx.x;
    const int h = t & 3;

    __shared__ float red[256];
    __shared__ float shmax[4], shsum[4];
    __shared__ float sacc[256 * 17];

    float* attn_c = (write_attn ? attn_out : g_attn_scratch) + (size_t)c * NLH;

    // ---- pass 1: per-head max over matching entries ----
    float m = -3.0e38f;
    for (int idx = t; idx < NLH; idx += 256) {
        int n = idx >> 3;               // idx = ((n*L)+l)*H + h
        if (load_comp(comp, n) == c) m = fmaxf(m, g_logits[idx]);
    }
    red[t] = m; __syncthreads();
    for (int s = 128; s >= 4; s >>= 1) {
        if (t < s) red[t] = fmaxf(red[t], red[t + s]);
        __syncthreads();
    }
    if (t < 4) shmax[t] = red[t];
    __syncthreads();

    // ---- pass 2: exp, sum, unnormalized attn, weighted-value partials ----
    const float mx = shmax[h];
    float ssum = 0.f;
    float acc[D_];
#pragma unroll
    for (int d = 0; d < D_; d++) acc[d] = 0.f;

    for (int idx = t; idx < NLH; idx += 256) {
        int n = idx >> 3;
        float e = 0.f;
        if (load_comp(comp, n) == c) {
            e = __expf(g_logits[idx] - mx);
            const float4* v4 = (const float4*)(g_value + (size_t)idx * D_);
            float4 a = v4[0], b = v4[1], cc = v4[2], dd = v4[3];
            acc[0]  = fmaf(e, a.x,  acc[0]);  acc[1]  = fmaf(e, a.y,  acc[1]);
            acc[2]  = fmaf(e, a.z,  acc[2]);  acc[3]  = fmaf(e, a.w,  acc[3]);
            acc[4]  = fmaf(e, b.x,  acc[4]);  acc[5]  = fmaf(e, b.y,  acc[5]);
            acc[6]  = fmaf(e, b.z,  acc[6]);  acc[7]  = fmaf(e, b.w,  acc[7]);
            acc[8]  = fmaf(e, cc.x, acc[8]);  acc[9]  = fmaf(e, cc.y, acc[9]);
            acc[10] = fmaf(e, cc.z, acc[10]); acc[11] = fmaf(e, cc.w, acc[11]);
            acc[12] = fmaf(e, dd.x, acc[12]); acc[13] = fmaf(e, dd.y, acc[13]);
            acc[14] = fmaf(e, dd.z, acc[14]); acc[15] = fmaf(e, dd.w, acc[15]);
        }
        attn_c[idx] = e;
        ssum += e;
    }
    red[t] = ssum; __syncthreads();
    for (int s = 128; s >= 4; s >>= 1) {
        if (t < s) red[t] += red[t + s];
        __syncthreads();
    }
    if (t < 4) shsum[t] = red[t];
    __syncthreads();

    // ---- pass 3: normalize attn in place ----
    const float rinv = 1.f / shsum[h];
    for (int idx = t; idx < NLH; idx += 256) attn_c[idx] *= rinv;

    // ---- reduce value partials across threads (same h) ----
#pragma unroll
    for (int d = 0; d < D_; d++) sacc[t*17 + d] = acc[d];
    __syncthreads();
    for (int s = 128; s >= 4; s >>= 1) {
        if (t < s) {
#pragma unroll
            for (int d = 0; d < D_; d++) sacc[t*17 + d] += sacc[(t+s)*17 + d];
        }
        __syncthreads();
    }
    // sacc[h*17 + d] now holds unnormalized out[c,h,d]

    // ---- final LayerNorm over d, write out ----
    if (t < 64) {
        int hh = t >> 4, d = t & 15;
        float x = sacc[hh*17 + d] * (1.f / shsum[hh]);
        float s1 = x;
#pragma unroll
        for (int off = 8; off >= 1; off >>= 1) s1 += __shfl_xor_sync(0xffffffffu, s1, off);
        float mu = s1 * (1.f/16.f);
        float dl = x - mu;
        float vv = dl * dl;
#pragma unroll
        for (int off = 8; off >= 1; off >>= 1) vv += __shfl_xor_sync(0xffffffffu, vv, off);
        float var = vv * (1.f/16.f);
        out[c * (H_*D_) + hh*D_ + d] = fmaf(dl * rsqrtf(var + EPS), out_gamma[d], out_beta[d]);
    }

    if (write_uid && t == 0) uid_out[c] = (float)c;
}

// ---------------------------------------------------------------------------
extern "C" void kernel_launch(void* const* d_in, const int* in_sizes, int n_in,
                              void* d_out, int out_size) {
    const float* feat      = (const float*)d_in[0];
    const float* query     = (const float*)d_in[1];
    const float* kw0       = (const float*)d_in[2];
    const float* kb0       = (const float*)d_in[3];
    const float* kw1       = (const float*)d_in[4];
    const float* kb1       = (const float*)d_in[5];
    const float* vw0       = (const float*)d_in[6];
    const float* vb0       = (const float*)d_in[7];
    const float* vw1       = (const float*)d_in[8];
    const float* vb1       = (const float*)d_in[9];
    const float* key_gamma = (const float*)d_in[10];
    const float* key_beta  = (const float*)d_in[11];
    const float* out_gamma = (const float*)d_in[12];
    const float* out_beta  = (const float*)d_in[13];
    const int*   comp      = (const int*)  d_in[14];   // int32 or int64; detected on device

    float* out = (float*)d_out;

    const int SZ_OUT  = C_ * H_ * D_;      // 2048
    const int SZ_ATTN = C_ * NLH;          // 524288
    const int full_attn = (out_size >= SZ_OUT + SZ_ATTN) ? 1 : 0;
    const int full_uid  = (out_size >= SZ_OUT + SZ_ATTN + C_) ? 1 : 0;

    float* attn_out = full_attn ? (out + SZ_OUT) : (float*)nullptr;
    float* uid_out  = full_uid  ? (out + SZ_OUT + SZ_ATTN) : (float*)nullptr;

    detect_dtype_kernel<<<1, 256>>>(comp);

    ffn_kernel<<<N_ * L_, 128>>>(feat, query, kw0, kb0, kw1, kb1,
                                 vw0, vb0, vw1, vb1, key_gamma, key_beta);

    softmax_out_kernel<<<C_, 256>>>(comp, out_gamma, out_beta,
                                    out, attn_out, uid_out, full_attn, full_uid);
}

// round 2
// speedup vs baseline: 1.4830x; 1.4830x over previous
#include <cuda_runtime.h>

#define N_  2048
#define L_  2
#define H_  4
#define D_  16
#define F_  64
#define E_  64
#define C_  32
#define NLH (N_*L_*H_)          // 16384
#define EPS 1e-5f

// Scratch (device globals — no allocation allowed)
__device__ float g_logits[NLH];            // 64 KB
__device__ float g_value [NLH * D_];       // 1 MB
__device__ float g_attn_scratch[C_ * NLH]; // 2 MB fallback if attn not in d_out

// ---------------------------------------------------------------------------
__device__ __forceinline__ float warp_sum16(float v) {
    v += __shfl_xor_sync(0xffffffffu, v, 1);
    v += __shfl_xor_sync(0xffffffffu, v, 2);
    v += __shfl_xor_sync(0xffffffffu, v, 4);
    v += __shfl_xor_sync(0xffffffffu, v, 8);
    return v;
}

// ---------------------------------------------------------------------------
// One FFN path for one (n,l,h). Fully-coalesced weight streaming:
//  - step s: lanes 0-15 hold row 2s of w0, lanes 16-31 row 2s+1
//    (one LDG.128 across the warp = 512B contiguous, nL=4)
//  - w1 read fused: per step one LDG.32 across warp = rows {2s,2s+1} x 16 d
//    = exactly one 128B line (nL=1)
// Returns LN'd output element for d = lane&15 (replicated in both halves).
// ---------------------------------------------------------------------------
__device__ __forceinline__ float ffn_path(
    const float* __restrict__ w0, const float* __restrict__ b0,
    const float* __restrict__ w1, const float* __restrict__ b1,
    float4 f4, int lane, float gd, float bd)
{
    const int l16  = lane & 15;
    const int half = lane >> 4;

    const float b0a = b0[lane];        // f = 0..31
    const float b0b = b0[32 + lane];   // f = 32..63

    const float* w0p = w0 + half * E_ + l16 * 4;  // row (2s+half), cols 4*l16..
    const float* w1p = w1 + half * D_ + l16;      // row (2s+half), col l16

    float acc = 0.f;                   // partial out[d=l16] over my half's f's
#pragma unroll
    for (int s = 0; s < 32; s++) {
        float4 w = *(const float4*)(w0p + s * 2 * E_);
        float t = fmaf(w.x, f4.x, fmaf(w.y, f4.y, fmaf(w.z, f4.z, w.w * f4.w)));
        t = warp_sum16(t);             // dot(feat, w0[f,:]) in all lanes of half
        float bsrc = (s < 16) ? b0a : b0b;                 // static select
        float bv = __shfl_sync(0xffffffffu, bsrc, 2 * s + half); // mod-32 wrap
        float h = fmaxf(t + bv, 0.f);
        acc = fmaf(h, w1p[s * 2 * D_], acc);
    }

    // combine even-f (lanes 0-15) and odd-f (lanes 16-31) partials
    float x = acc + __shfl_xor_sync(0xffffffffu, acc, 16) + b1[l16];

    // LayerNorm over the 16 d-values (replicated in both halves)
    float mu  = warp_sum16(x) * (1.f / 16.f);
    float dl  = x - mu;
    float var = warp_sum16(dl * dl) * (1.f / 16.f);
    return fmaf(dl * rsqrtf(var + EPS), gd, bd);
}

// ---------------------------------------------------------------------------
// Kernel 1: per-node FFNs (key + value), logits, LN'd values.
// grid = N*L blocks, 128 threads (one warp per head). No smem, no block sync.
// ---------------------------------------------------------------------------
__global__ __launch_bounds__(128) void ffn_kernel(
    const float* __restrict__ feat,  const float* __restrict__ query,
    const float* __restrict__ kw0,   const float* __restrict__ kb0,
    const float* __restrict__ kw1,   const float* __restrict__ kb1,
    const float* __restrict__ vw0,   const float* __restrict__ vb0,
    const float* __restrict__ vw1,   const float* __restrict__ vb1,
    const float* __restrict__ key_gamma, const float* __restrict__ key_beta)
{
    const int nl   = blockIdx.x;
    const int wid  = threadIdx.x >> 5;
    const int lane = threadIdx.x & 31;
    const int l16  = lane & 15;
    const int nlh  = nl * H_ + wid;

    const float4 f4 = ((const float4*)(feat + (size_t)nl * E_))[l16];
    const float gd = key_gamma[l16];
    const float bd = key_beta [l16];

    const size_t o0 = (size_t)nlh * (F_ * E_);
    const size_t o1 = (size_t)nlh * (F_ * D_);
    const size_t ob = (size_t)nlh * F_;
    const size_t od = (size_t)nlh * D_;

    // key path -> logit
    float kln = ffn_path(kw0 + o0, kb0 + ob, kw1 + o1, kb1 + od, f4, lane, gd, bd);
    float p = kln * query[od + l16];
    p = warp_sum16(p);
    if (lane == 0) g_logits[nlh] = p;

    // value path (reference reuses key_gamma/key_beta here)
    float vln = ffn_path(vw0 + o0, vb0 + ob, vw1 + o1, vb1 + od, f4, lane, gd, bd);
    if (lane < D_) g_value[od + lane] = vln;
}

// ---------------------------------------------------------------------------
// Kernel 2: per-component masked softmax over (n,l) jointly per head,
// attention-weighted sum of values, final LayerNorm.
// grid = C blocks, 256 threads. Thread t always handles head h = t & 3.
// Inline component_id dtype detection (int64 vs int32) + smem match mask.
// ---------------------------------------------------------------------------
__global__ __launch_bounds__(256) void softmax_out_kernel(
    const int* __restrict__ comp,
    const float* __restrict__ out_gamma, const float* __restrict__ out_beta,
    float* __restrict__ out, float* __restrict__ attn_out,
    float* __restrict__ uid_out, int write_attn, int write_uid)
{
    const int c = blockIdx.x;
    const int t = threadIdx.x;
    const int h = t & 3;

    __shared__ int s_nz;
    __shared__ unsigned char smask[N_];
    __shared__ float red[256];
    __shared__ float shmax[4], shsum[4];
    __shared__ float sacc[256 * 17];

    // ---- dtype detection: int64 iff all odd 32-bit words in [0,N_) are 0.
    // Reads only the first N_ words -> in-bounds for both dtypes.
    if (t == 0) s_nz = 0;
    __syncthreads();
    {
        int vz = 0;
        for (int i = t; i < N_ / 2; i += 256) vz |= comp[2 * i + 1];
        if (vz) atomicOr(&s_nz, 1);
    }
    __syncthreads();
    const int is64 = (s_nz == 0);

    // ---- smem match mask per node ----
    for (int n = t; n < N_; n += 256) {
        int cid = is64 ? comp[2 * n] : comp[n];
        smask[n] = (cid == c);
    }
    __syncthreads();

    float* attn_c = (write_attn ? attn_out : g_attn_scratch) + (size_t)c * NLH;

    // ---- pass 1: per-head max over matching entries ----
    float m = -3.0e38f;
    for (int idx = t; idx < NLH; idx += 256) {
        int n = idx >> 3;               // idx = ((n*L)+l)*H + h
        if (smask[n]) m = fmaxf(m, g_logits[idx]);
    }
    red[t] = m; __syncthreads();
    for (int s = 128; s >= 4; s >>= 1) {
        if (t < s) red[t] = fmaxf(red[t], red[t + s]);
        __syncthreads();
    }
    if (t < 4) shmax[t] = red[t];
    __syncthreads();

    // ---- pass 2: exp, sum, unnormalized attn, weighted-value partials ----
    const float mx = shmax[h];
    float ssum = 0.f;
    float acc[D_];
#pragma unroll
    for (int d = 0; d < D_; d++) acc[d] = 0.f;

    for (int idx = t; idx < NLH; idx += 256) {
        int n = idx >> 3;
        float e = 0.f;
        if (smask[n]) {
            e = __expf(g_logits[idx] - mx);
            const float4* v4 = (const float4*)(g_value + (size_t)idx * D_);
            float4 a = v4[0], b = v4[1], cc = v4[2], dd = v4[3];
            acc[0]  = fmaf(e, a.x,  acc[0]);  acc[1]  = fmaf(e, a.y,  acc[1]);
            acc[2]  = fmaf(e, a.z,  acc[2]);  acc[3]  = fmaf(e, a.w,  acc[3]);
            acc[4]  = fmaf(e, b.x,  acc[4]);  acc[5]  = fmaf(e, b.y,  acc[5]);
            acc[6]  = fmaf(e, b.z,  acc[6]);  acc[7]  = fmaf(e, b.w,  acc[7]);
            acc[8]  = fmaf(e, cc.x, acc[8]);  acc[9]  = fmaf(e, cc.y, acc[9]);
            acc[10] = fmaf(e, cc.z, acc[10]); acc[11] = fmaf(e, cc.w, acc[11]);
            acc[12] = fmaf(e, dd.x, acc[12]); acc[13] = fmaf(e, dd.y, acc[13]);
            acc[14] = fmaf(e, dd.z, acc[14]); acc[15] = fmaf(e, dd.w, acc[15]);
        }
        attn_c[idx] = e;
        ssum += e;
    }
    red[t] = ssum; __syncthreads();
    for (int s = 128; s >= 4; s >>= 1) {
        if (t < s) red[t] += red[t + s];
        __syncthreads();
    }
    if (t < 4) shsum[t] = red[t];
    __syncthreads();

    // ---- pass 3: normalize attn in place ----
    const float rinv = 1.f / shsum[h];
    for (int idx = t; idx < NLH; idx += 256) attn_c[idx] *= rinv;

    // ---- reduce value partials across threads (same h) ----
#pragma unroll
    for (int d = 0; d < D_; d++) sacc[t*17 + d] = acc[d];
    __syncthreads();
    for (int s = 128; s >= 4; s >>= 1) {
        if (t < s) {
#pragma unroll
            for (int d = 0; d < D_; d++) sacc[t*17 + d] += sacc[(t+s)*17 + d];
        }
        __syncthreads();
    }
    // sacc[h*17 + d] now holds unnormalized out[c,h,d]

    // ---- final LayerNorm over d, write out ----
    if (t < 64) {
        int hh = t >> 4, d = t & 15;
        float x = sacc[hh*17 + d] * (1.f / shsum[hh]);
        float s1 = x;
#pragma unroll
        for (int off = 8; off >= 1; off >>= 1) s1 += __shfl_xor_sync(0xffffffffu, s1, off);
        float mu = s1 * (1.f/16.f);
        float dl = x - mu;
        float vv = dl * dl;
#pragma unroll
        for (int off = 8; off >= 1; off >>= 1) vv += __shfl_xor_sync(0xffffffffu, vv, off);
        float var = vv * (1.f/16.f);
        out[c * (H_*D_) + hh*D_ + d] = fmaf(dl * rsqrtf(var + EPS), out_gamma[d], out_beta[d]);
    }

    if (write_uid && t == 0) uid_out[c] = (float)c;
}

// ---------------------------------------------------------------------------
extern "C" void kernel_launch(void* const* d_in, const int* in_sizes, int n_in,
                              void* d_out, int out_size) {
    const float* feat      = (const float*)d_in[0];
    const float* query     = (const float*)d_in[1];
    const float* kw0       = (const float*)d_in[2];
    const float* kb0       = (const float*)d_in[3];
    const float* kw1       = (const float*)d_in[4];
    const float* kb1       = (const float*)d_in[5];
    const float* vw0       = (const float*)d_in[6];
    const float* vb0       = (const float*)d_in[7];
    const float* vw1       = (const float*)d_in[8];
    const float* vb1       = (const float*)d_in[9];
    const float* key_gamma = (const float*)d_in[10];
    const float* key_beta  = (const float*)d_in[11];
    const float* out_gamma = (const float*)d_in[12];
    const float* out_beta  = (const float*)d_in[13];
    const int*   comp      = (const int*)  d_in[14];   // int32 or int64; detected on device

    float* out = (float*)d_out;

    const int SZ_OUT  = C_ * H_ * D_;      // 2048
    const int SZ_ATTN = C_ * NLH;          // 524288
    const int full_attn = (out_size >= SZ_OUT + SZ_ATTN) ? 1 : 0;
    const int full_uid  = (out_size >= SZ_OUT + SZ_ATTN + C_) ? 1 : 0;

    float* attn_out = full_attn ? (out + SZ_OUT) : (float*)nullptr;
    float* uid_out  = full_uid  ? (out + SZ_OUT + SZ_ATTN) : (float*)nullptr;

    ffn_kernel<<<N_ * L_, 128>>>(feat, query, kw0, kb0, kw1, kb1,
                                 vw0, vb0, vw1, vb1, key_gamma, key_beta);

    softmax_out_kernel<<<C_, 256>>>(comp, out_gamma, out_beta,
                                    out, attn_out, uid_out, full_attn, full_uid);
}